// round 6
// baseline (speedup 1.0000x reference)
#include <cuda_runtime.h>

// Shapes (fixed): h=8, n=8, d=512, c=64, c2=32, i=96, kk=3
// Output layout: [ T (8*64*96*96) | M (8*8*32) | P (8*8*64*96*96) | w (same as P) ]
#define T_OFF   0
#define M_OFF   4718592
#define P_OFF   4720640
#define W_OFF   42469376
#define INV24   (1.0f/24.0f)

// ---------------- scratch (device globals; no allocation) ----------------
__device__ float g_M[2048];                       // [n][h][32]
__device__ float g_Ak[4096],  g_Av[4096];         // [n][h][64]
__device__ float g_Bxk[49152], g_Byk[49152];      // [h][64][96]
__device__ float g_Bxv[49152], g_Byv[49152];      // [h][64][96]
__device__ float g_swX[36864], g_swY[36864];      // [cls][tap][o][cin] (4096 per slot)
__device__ float g_U[36864];                      // [n][h][o][xc][ky]
__device__ float g_Vx[442368], g_Vy[442368];      // [h][o][cls][tap][96]
__device__ float g_EX[147456];                    // [h][o][yc][96]
__device__ float g_EY[1179648];                   // [n][h][o][xc][96]
__device__ float g_VY[393216];                    // [n][h][o][96]

// ---------------- K1: per-head linear -> BN(train) -> ReLU -> M ----------
__global__ void k_embed(const float* __restrict__ X, const float* __restrict__ lw,
                        const float* __restrict__ lb, const float* __restrict__ gam,
                        const float* __restrict__ bet, float* __restrict__ outM) {
    int h = blockIdx.x;           // 8 blocks
    int t = threadIdx.x;          // 256 threads
    __shared__ float Xs[4096];    // X[h] : 8x512
    __shared__ float ys[256];     // y[n][c]
    __shared__ float mu_s[32], iv_s[32];
    const float* Xh = X + h * 4096;
    for (int k = t; k < 4096; k += 256) Xs[k] = Xh[k];
    __syncthreads();
    int nn = t >> 5, cc = t & 31;
    const float* wr = lw + (h * 32 + cc) * 512;
    const float* xr = Xs + nn * 512;
    float acc = 0.f;
    #pragma unroll 8
    for (int d = 0; d < 512; d++) acc += xr[d] * wr[d];
    acc += lb[h * 32 + cc];
    ys[t] = acc;
    __syncthreads();
    if (t < 32) {
        float m = 0.f;
        for (int j = 0; j < 8; j++) m += ys[j * 32 + t];
        m *= 0.125f;
        float v = 0.f;
        for (int j = 0; j < 8; j++) { float d0 = ys[j * 32 + t] - m; v += d0 * d0; }
        v *= 0.125f;
        mu_s[t] = m;
        iv_s[t] = rsqrtf(v + 1e-5f);
    }
    __syncthreads();
    float val = (acc - mu_s[cc]) * iv_s[cc] * gam[h * 32 + cc] + bet[h * 32 + cc];
    val = fmaxf(val, 0.f);
    int idx = (nn * 8 + h) * 32 + cc;   // M[n][h][c]
    g_M[idx]  = val;
    outM[idx] = val;
}

// ---------------- K2: A_k / A_v  (constant term of kp/vp) ----------------
__global__ void k_axes(const float* __restrict__ kw, const float* __restrict__ kb,
                       const float* __restrict__ vw, const float* __restrict__ vb) {
    int t = blockIdx.x * 256 + threadIdx.x;   // 4096 = n*h*64
    if (t >= 4096) return;
    int d = t & 63, h = (t >> 6) & 7, n = t >> 9;
    const float* Mr  = g_M + (n * 8 + h) * 32;
    const float* kwr = kw + (h * 64 + d) * 64;
    const float* vwr = vw + (h * 64 + d) * 64;
    float ak = 0.f, av = 0.f;
    #pragma unroll 8
    for (int c = 0; c < 32; c++) {
        float m = Mr[c];
        ak += (kwr[c] + kwr[c + 32]) * m;
        av += (vwr[c] + vwr[c + 32]) * m;
    }
    g_Ak[t] = ak + kb[h * 64 + d];
    g_Av[t] = av + vb[h * 64 + d];
}

// ---------------- K3: Bx/By tables (col/row terms of kp/vp) --------------
__global__ void k_btab(const float* __restrict__ kw, const float* __restrict__ vw,
                       const float* __restrict__ px, const float* __restrict__ py) {
    int t = blockIdx.x * 256 + threadIdx.x;   // 49152 = h*64*96
    if (t >= 49152) return;
    int pos = t % 96;
    int hd  = t / 96;
    int d = hd & 63, h = hd >> 6;
    const float* kwr = kw + (h * 64 + d) * 64;
    const float* vwr = vw + (h * 64 + d) * 64;
    float bxk = 0.f, byk = 0.f, bxv = 0.f, byv = 0.f;
    #pragma unroll 8
    for (int c = 0; c < 32; c++) {
        float pxv = px[c * 96 + pos];
        float pyv = py[c * 96 + pos];
        bxk += kwr[c]      * pxv;
        byk += kwr[c + 32] * pyv;
        bxv += vwr[c]      * pxv;
        byv += vwr[c + 32] * pyv;
    }
    g_Bxk[t] = bxk; g_Byk[t] = byk; g_Bxv[t] = bxv; g_Byv[t] = byv;
}

// ------------ K4: border-class summed conv weights swX / swY -------------
__global__ void k_swtab(const float* __restrict__ sw) {
    int t = blockIdx.x * 256 + threadIdx.x;   // 4096 = 64*64 (o,cin)
    if (t >= 4096) return;
    float s[3][3];
    const float* p = sw + t * 9;
    #pragma unroll
    for (int ky = 0; ky < 3; ky++)
        #pragma unroll
        for (int kx = 0; kx < 3; kx++) s[ky][kx] = p[ky * 3 + kx];
    #pragma unroll
    for (int xc = 0; xc < 3; xc++)
        #pragma unroll
        for (int ky = 0; ky < 3; ky++) {
            float v = (xc == 0) ? (s[ky][1] + s[ky][2])
                    : (xc == 1) ? (s[ky][0] + s[ky][1] + s[ky][2])
                                : (s[ky][0] + s[ky][1]);
            g_swX[(xc * 3 + ky) * 4096 + t] = v;
        }
    #pragma unroll
    for (int yc = 0; yc < 3; yc++)
        #pragma unroll
        for (int kx = 0; kx < 3; kx++) {
            float v = (yc == 0) ? (s[1][kx] + s[2][kx])
                    : (yc == 1) ? (s[0][kx] + s[1][kx] + s[2][kx])
                                : (s[0][kx] + s[1][kx]);
            g_swY[(yc * 3 + kx) * 4096 + t] = v;
        }
}

// ---------------- K5: U[n,h,o,xc,ky] = sum_cin swX * A_k ----------------
__global__ void k_u() {
    int t = blockIdx.x * 256 + threadIdx.x;   // 36864
    if (t >= 36864) return;
    int tap = t % 3; int r = t / 3;
    int cls = r % 3; r /= 3;
    int o = r % 64;  r /= 64;
    int h = r % 8;   int n = r / 8;
    const float* wv = g_swX + (cls * 3 + tap) * 4096 + o * 64;
    const float* ap = g_Ak + (n * 8 + h) * 64;
    float acc = 0.f;
    #pragma unroll 8
    for (int c = 0; c < 64; c++) acc += wv[c] * ap[c];
    g_U[t] = acc;
}

// ------------ K6: Vx/Vy tap tables (GEMM-lite over cin) ------------------
__global__ void k_vtab() {
    int t = blockIdx.x * 256 + threadIdx.x;   // 442368 = h*64*3*3*96
    if (t >= 442368) return;
    int pos = t % 96; int r = t / 96;
    int tap = r % 3;  r /= 3;
    int cls = r % 3;  r /= 3;
    int o = r % 64;   int h = r / 64;
    const float* wx = g_swX + (cls * 3 + tap) * 4096 + o * 64;  // for Vy
    const float* wy = g_swY + (cls * 3 + tap) * 4096 + o * 64;  // for Vx
    const float* byp = g_Byk + h * 6144 + pos;  // stride 96 per cin
    const float* bxp = g_Bxk + h * 6144 + pos;
    float vy = 0.f, vx = 0.f;
    #pragma unroll 8
    for (int c = 0; c < 64; c++) {
        vy += wx[c] * byp[c * 96];
        vx += wy[c] * bxp[c * 96];
    }
    g_Vy[t] = vy;
    g_Vx[t] = vx;
}

// ---------------- K7: EX = exp(GX/24) -------------------------------------
__global__ void k_ex() {
    int t = blockIdx.x * 256 + threadIdx.x;   // 147456 = h*64*3*96
    if (t >= 147456) return;
    int jj = t % 96; int r = t / 96;
    int yc = r % 3;  r /= 3;
    int o = r % 64;  int h = r / 64;
    int base = ((h * 64 + o) * 3 + yc) * 3 * 96;
    float acc = 0.f;
    #pragma unroll
    for (int kx = 0; kx < 3; kx++) {
        int j2 = jj + kx - 1;
        if (j2 >= 0 && j2 < 96) acc += g_Vx[base + kx * 96 + j2];
    }
    g_EX[t] = expf(acc * INV24);
}

// ---------------- K8: EY = exp((GA + GY + sb)/24) --------------------------
__global__ void k_ey(const float* __restrict__ sb) {
    int t = blockIdx.x * 256 + threadIdx.x;   // 1179648 = n*h*64*3*96
    if (t >= 1179648) return;
    int ii = t % 96; int r = t / 96;
    int xc = r % 3;  r /= 3;
    int o = r % 64;  r /= 64;
    int h = r % 8;   int n = r / 8;
    int ub = (((n * 8 + h) * 64 + o) * 3 + xc) * 3;
    int vb = ((h * 64 + o) * 3 + xc) * 3 * 96;
    float acc = sb[o];
    #pragma unroll
    for (int ky = 0; ky < 3; ky++) {
        int i2 = ii + ky - 1;
        if (i2 >= 0 && i2 < 96) acc += g_U[ub + ky] + g_Vy[vb + ky * 96 + i2];
    }
    g_EY[t] = expf(acc * INV24);
}

// ---------------- K9: VY = A_v + By_v --------------------------------------
__global__ void k_vy() {
    int t = blockIdx.x * 256 + threadIdx.x;   // 393216 = n*h*64*96
    if (t >= 393216) return;
    int ii = t % 96; int r = t / 96;
    int o = r % 64;  r /= 64;
    int h = r % 8;   int n = r / 8;
    g_VY[t] = g_Av[(n * 8 + h) * 64 + o] + g_Byv[(h * 64 + o) * 96 + ii];
}

// ---------------- K10: main — softmax-free hot loop, writes T, w, P -------
__global__ void __launch_bounds__(384) k_main(const float* __restrict__ px,
                                              const float* __restrict__ py,
                                              float* __restrict__ out) {
    int jj = threadIdx.x;                              // 0..95
    int ii = blockIdx.x * 4 + threadIdx.y;             // 0..95
    int o  = blockIdx.y;                               // 0..63
    int n  = blockIdx.z;                               // 0..7
    int p  = ii * 96 + jj;
    int yc = (ii == 0) ? 0 : ((ii == 95) ? 2 : 1);
    int xc = (jj == 0) ? 0 : ((jj == 95) ? 2 : 1);

    int eyB = (n * 512 + o) * 288 + xc * 96 + ii;      // +h*18432
    int exB = (o * 3 + yc) * 96 + jj;                  // +h*18432
    int vyB = (n * 512 + o) * 96 + ii;                 // +h*6144
    int bxB = o * 96 + jj;                             // +h*6144

    float e[8];
    float sum = 0.f, acc = 0.f;
    #pragma unroll
    for (int h = 0; h < 8; h++) {
        float eh = g_EY[eyB + h * 18432] * g_EX[exB + h * 18432];
        float vp = g_VY[vyB + h * 6144] + g_Bxv[bxB + h * 6144];
        sum += eh;
        acc += eh * vp;
        e[h] = eh;
    }
    float inv = __fdividef(1.0f, sum);

    out[T_OFF + (n * 64 + o) * 9216 + p] = acc * inv;

    float pAdd = (o < 32) ? px[o * 96 + jj] : py[(o - 32) * 96 + ii];
    int wB = W_OFF + (n * 512 + o) * 9216 + p;         // +h*589824
    int pB = P_OFF + (n * 512 + o) * 9216 + p;
    int mB = n * 256 + (o & 31);                       // +h*32
    #pragma unroll
    for (int h = 0; h < 8; h++) {
        out[wB + h * 589824] = e[h] * inv;
        out[pB + h * 589824] = g_M[mB + h * 32] + pAdd;
    }
}

// ---------------- launch ----------------------------------------------------
extern "C" void kernel_launch(void* const* d_in, const int* in_sizes, int n_in,
                              void* d_out, int out_size) {
    const float* X     = (const float*)d_in[0];
    const float* lin_w = (const float*)d_in[1];
    const float* lin_b = (const float*)d_in[2];
    const float* gam   = (const float*)d_in[3];
    const float* bet   = (const float*)d_in[4];
    const float* px    = (const float*)d_in[5];
    const float* py    = (const float*)d_in[6];
    const float* kw    = (const float*)d_in[7];
    const float* kb    = (const float*)d_in[8];
    const float* vw    = (const float*)d_in[9];
    const float* vb    = (const float*)d_in[10];
    const float* sw    = (const float*)d_in[11];
    const float* sb    = (const float*)d_in[12];
    float* out = (float*)d_out;

    k_embed<<<8, 256>>>(X, lin_w, lin_b, gam, bet, out + M_OFF);
    k_axes<<<16, 256>>>(kw, kb, vw, vb);
    k_btab<<<192, 256>>>(kw, vw, px, py);
    k_swtab<<<16, 256>>>(sw);
    k_u<<<144, 256>>>();
    k_vtab<<<1728, 256>>>();
    k_ex<<<576, 256>>>();
    k_ey<<<4608, 256>>>(sb);
    k_vy<<<1536, 256>>>();
    k_main<<<dim3(24, 64, 8), dim3(96, 4)>>>(px, py, out);
}

// round 7
// speedup vs baseline: 1.2221x; 1.2221x over previous
#include <cuda_runtime.h>

// Shapes (fixed): h=8, n=8, d=512, c=64, c2=32, i=96, kk=3
// Output layout: [ T (8*64*96*96) | M (8*8*32) | P (8*8*64*96*96) | w (same as P) ]
#define T_OFF   0
#define M_OFF   4718592
#define P_OFF   4720640
#define W_OFF   42469376
#define INV24   (1.0f/24.0f)

// ---------------- scratch (device globals; no allocation) ----------------
__device__ __align__(16) float g_M[2048];                       // [n][h][32]
__device__ __align__(16) float g_Ak[4096],  g_Av[4096];         // [n][h][64]
__device__ __align__(16) float g_Bxk[49152], g_Byk[49152];      // [h][64][96]
__device__ __align__(16) float g_Bxv[49152], g_Byv[49152];      // [h][64][96]
__device__ __align__(16) float g_swX[36864], g_swY[36864];      // [cls][tap][o][cin]
__device__ __align__(16) float g_U[36864];                      // [n][h][o][xc][ky]
__device__ __align__(16) float g_Vx[442368], g_Vy[442368];      // [h][o][cls][tap][96]
__device__ __align__(16) float g_EX[147456];                    // [h][o][yc][96]
__device__ __align__(16) float g_EY[1179648];                   // [n][h][o][xc][96]
__device__ __align__(16) float g_VY[393216];                    // [n][h][o][96]

// ---------------- K1: per-head linear -> BN(train) -> ReLU -> M ----------
__global__ void k_embed(const float* __restrict__ X, const float* __restrict__ lw,
                        const float* __restrict__ lb, const float* __restrict__ gam,
                        const float* __restrict__ bet, float* __restrict__ outM) {
    int h = blockIdx.x;           // 8 blocks
    int t = threadIdx.x;          // 256 threads
    __shared__ float Xs[4096];
    __shared__ float ys[256];
    __shared__ float mu_s[32], iv_s[32];
    const float* Xh = X + h * 4096;
    for (int k = t; k < 4096; k += 256) Xs[k] = Xh[k];
    __syncthreads();
    int nn = t >> 5, cc = t & 31;
    const float* wr = lw + (h * 32 + cc) * 512;
    const float* xr = Xs + nn * 512;
    float acc = 0.f;
    #pragma unroll 8
    for (int d = 0; d < 512; d++) acc += xr[d] * wr[d];
    acc += lb[h * 32 + cc];
    ys[t] = acc;
    __syncthreads();
    if (t < 32) {
        float m = 0.f;
        for (int j = 0; j < 8; j++) m += ys[j * 32 + t];
        m *= 0.125f;
        float v = 0.f;
        for (int j = 0; j < 8; j++) { float d0 = ys[j * 32 + t] - m; v += d0 * d0; }
        v *= 0.125f;
        mu_s[t] = m;
        iv_s[t] = rsqrtf(v + 1e-5f);
    }
    __syncthreads();
    float val = (acc - mu_s[cc]) * iv_s[cc] * gam[h * 32 + cc] + bet[h * 32 + cc];
    val = fmaxf(val, 0.f);
    int idx = (nn * 8 + h) * 32 + cc;   // M[n][h][c]
    g_M[idx]  = val;
    outM[idx] = val;
}

// --------- K2 (fused): axes (b<16) | btab (16..207) | swtab (208..223) ----
__global__ void k_tab1(const float* __restrict__ kw, const float* __restrict__ kb,
                       const float* __restrict__ vw, const float* __restrict__ vb,
                       const float* __restrict__ px, const float* __restrict__ py,
                       const float* __restrict__ sw) {
    int b = blockIdx.x, tid = threadIdx.x;
    if (b < 16) {
        // ---- axes: A_k/A_v constant terms (4096 work items) ----
        int t = b * 256 + tid;
        int d = t & 63, h = (t >> 6) & 7, n = t >> 9;
        const float* Mr  = g_M + (n * 8 + h) * 32;
        const float* kwr = kw + (h * 64 + d) * 64;
        const float* vwr = vw + (h * 64 + d) * 64;
        float ak = 0.f, av = 0.f;
        #pragma unroll 8
        for (int c = 0; c < 32; c++) {
            float m = Mr[c];
            ak += (kwr[c] + kwr[c + 32]) * m;
            av += (vwr[c] + vwr[c + 32]) * m;
        }
        g_Ak[t] = ak + kb[h * 64 + d];
        g_Av[t] = av + vb[h * 64 + d];
    } else if (b < 208) {
        // ---- btab: Bx/By tables (49152 work items) ----
        int t = (b - 16) * 256 + tid;
        int pos = t % 96;
        int hd  = t / 96;
        int d = hd & 63, h = hd >> 6;
        const float* kwr = kw + (h * 64 + d) * 64;
        const float* vwr = vw + (h * 64 + d) * 64;
        float bxk = 0.f, byk = 0.f, bxv = 0.f, byv = 0.f;
        #pragma unroll 8
        for (int c = 0; c < 32; c++) {
            float pxv = px[c * 96 + pos];
            float pyv = py[c * 96 + pos];
            bxk += kwr[c]      * pxv;
            byk += kwr[c + 32] * pyv;
            bxv += vwr[c]      * pxv;
            byv += vwr[c + 32] * pyv;
        }
        g_Bxk[t] = bxk; g_Byk[t] = byk; g_Bxv[t] = bxv; g_Byv[t] = byv;
    } else {
        // ---- swtab: border-class conv weight tables (4096 work items) ----
        int t = (b - 208) * 256 + tid;
        float s[3][3];
        const float* p = sw + t * 9;
        #pragma unroll
        for (int ky = 0; ky < 3; ky++)
            #pragma unroll
            for (int kx = 0; kx < 3; kx++) s[ky][kx] = p[ky * 3 + kx];
        #pragma unroll
        for (int xc = 0; xc < 3; xc++)
            #pragma unroll
            for (int ky = 0; ky < 3; ky++) {
                float v = (xc == 0) ? (s[ky][1] + s[ky][2])
                        : (xc == 1) ? (s[ky][0] + s[ky][1] + s[ky][2])
                                    : (s[ky][0] + s[ky][1]);
                g_swX[(xc * 3 + ky) * 4096 + t] = v;
            }
        #pragma unroll
        for (int yc = 0; yc < 3; yc++)
            #pragma unroll
            for (int kx = 0; kx < 3; kx++) {
                float v = (yc == 0) ? (s[1][kx] + s[2][kx])
                        : (yc == 1) ? (s[0][kx] + s[1][kx] + s[2][kx])
                                    : (s[0][kx] + s[1][kx]);
                g_swY[(yc * 3 + kx) * 4096 + t] = v;
            }
    }
}

// --------- K3 (fused): u (b<144) | vtab4 (144..575, float4) ---------------
__global__ void k_tab2() {
    int b = blockIdx.x, tid = threadIdx.x;
    if (b < 144) {
        // ---- U[n,h,o,xc,ky] = sum_cin swX * A_k  (36864 items) ----
        int t = b * 256 + tid;
        int tap = t % 3; int r = t / 3;
        int cls = r % 3; r /= 3;
        int o = r % 64;  r /= 64;
        int h = r % 8;   int n = r / 8;
        const float* wv = g_swX + (cls * 3 + tap) * 4096 + o * 64;
        const float* ap = g_Ak + (n * 8 + h) * 64;
        float acc = 0.f;
        #pragma unroll 8
        for (int c = 0; c < 64; c++) acc += wv[c] * ap[c];
        g_U[t] = acc;
    } else {
        // ---- Vx/Vy tap tables, float4 over pos (110592 items of 4) ----
        int t = (b - 144) * 256 + tid;
        int q = t % 24; int r = t / 24;
        int tap = r % 3;  r /= 3;
        int cls = r % 3;  r /= 3;
        int o = r % 64;   int h = r / 64;
        const float* wx = g_swX + (cls * 3 + tap) * 4096 + o * 64;  // -> Vy
        const float* wy = g_swY + (cls * 3 + tap) * 4096 + o * 64;  // -> Vx
        const float* byp = g_Byk + h * 6144 + q * 4;
        const float* bxp = g_Bxk + h * 6144 + q * 4;
        float4 vy = {0,0,0,0}, vx = {0,0,0,0};
        #pragma unroll 8
        for (int c = 0; c < 64; c++) {
            float wxc = wx[c], wyc = wy[c];
            float4 by = *(const float4*)(byp + c * 96);
            float4 bx = *(const float4*)(bxp + c * 96);
            vy.x += wxc * by.x; vy.y += wxc * by.y; vy.z += wxc * by.z; vy.w += wxc * by.w;
            vx.x += wyc * bx.x; vx.y += wyc * bx.y; vx.z += wyc * bx.z; vx.w += wyc * bx.w;
        }
        int base = ((((h * 64 + o) * 3 + cls) * 3 + tap) * 96) + q * 4;
        *(float4*)(g_Vy + base) = vy;
        *(float4*)(g_Vx + base) = vx;
    }
}

// --------- K4 (fused): ex (b<576) | ey (576..5183) | vy4 (5184..5567) ------
__global__ void k_tab3(const float* __restrict__ sb) {
    int b = blockIdx.x, tid = threadIdx.x;
    if (b < 576) {
        // ---- EX = exp(GX/24)  (147456 items) ----
        int t = b * 256 + tid;
        int jj = t % 96; int r = t / 96;
        int yc = r % 3;  r /= 3;
        int o = r % 64;  int h = r / 64;
        int base = ((h * 64 + o) * 3 + yc) * 3 * 96;
        float acc = 0.f;
        #pragma unroll
        for (int kx = 0; kx < 3; kx++) {
            int j2 = jj + kx - 1;
            if (j2 >= 0 && j2 < 96) acc += g_Vx[base + kx * 96 + j2];
        }
        g_EX[t] = expf(acc * INV24);
    } else if (b < 5184) {
        // ---- EY = exp((GA + GY + sb)/24)  (1179648 items) ----
        int t = (b - 576) * 256 + tid;
        int ii = t % 96; int r = t / 96;
        int xc = r % 3;  r /= 3;
        int o = r % 64;  r /= 64;
        int h = r % 8;   int n = r / 8;
        int ub = (((n * 8 + h) * 64 + o) * 3 + xc) * 3;
        int vb = ((h * 64 + o) * 3 + xc) * 3 * 96;
        float acc = sb[o];
        #pragma unroll
        for (int ky = 0; ky < 3; ky++) {
            int i2 = ii + ky - 1;
            if (i2 >= 0 && i2 < 96) acc += g_U[ub + ky] + g_Vy[vb + ky * 96 + i2];
        }
        g_EY[t] = expf(acc * INV24);
    } else {
        // ---- VY = A_v + By_v, float4 over ii (98304 items of 4) ----
        int t = (b - 5184) * 256 + tid;
        int q = t % 24; int r = t / 24;
        int o = r % 64;  r /= 64;
        int h = r % 8;   int n = r / 8;
        float av = g_Av[(n * 8 + h) * 64 + o];
        float4 by = *(const float4*)(g_Byv + (h * 64 + o) * 96 + q * 4);
        float4 vout = {av + by.x, av + by.y, av + by.z, av + by.w};
        *(float4*)(g_VY + ((n * 8 + h) * 64 + o) * 96 + q * 4) = vout;
    }
}

// ---------------- K5: main — float4 hot loop, writes T, w, P --------------
__global__ void __launch_bounds__(384) k_main(const float* __restrict__ px,
                                              const float* __restrict__ py,
                                              float* __restrict__ out) {
    int jq  = threadIdx.x;                           // 0..23 -> 4 jj each
    int jj0 = jq * 4;
    int ii  = blockIdx.x * 16 + threadIdx.y;         // 0..95
    int o   = blockIdx.y;                            // 0..63
    int n   = blockIdx.z;                            // 0..7
    int yc  = (ii == 0) ? 0 : ((ii == 95) ? 2 : 1);

    int eyB = (n * 512 + o) * 288 + ii;              // + xc*96 + h*18432
    int exB = (o * 3 + yc) * 96 + jj0;               // + h*18432
    int vyB = (n * 512 + o) * 96 + ii;               // + h*6144
    int bxB = o * 96 + jj0;                          // + h*6144

    float4 e[8];
    float4 sum = {0,0,0,0}, acc = {0,0,0,0};
    #pragma unroll
    for (int h = 0; h < 8; h++) {
        int hoff = h * 18432;
        float eyM = g_EY[eyB + 96 + hoff];
        float ey0 = (jq == 0)  ? g_EY[eyB + hoff]       : eyM;
        float ey3 = (jq == 23) ? g_EY[eyB + 192 + hoff] : eyM;
        float4 ex = *(const float4*)(g_EX + exB + hoff);
        float  vy = g_VY[vyB + h * 6144];
        float4 bx = *(const float4*)(g_Bxv + bxB + h * 6144);
        float4 eh;
        eh.x = ey0 * ex.x; eh.y = eyM * ex.y; eh.z = eyM * ex.z; eh.w = ey3 * ex.w;
        e[h] = eh;
        sum.x += eh.x; sum.y += eh.y; sum.z += eh.z; sum.w += eh.w;
        acc.x += eh.x * (vy + bx.x);
        acc.y += eh.y * (vy + bx.y);
        acc.z += eh.z * (vy + bx.z);
        acc.w += eh.w * (vy + bx.w);
    }
    float4 inv;
    inv.x = __fdividef(1.f, sum.x);
    inv.y = __fdividef(1.f, sum.y);
    inv.z = __fdividef(1.f, sum.z);
    inv.w = __fdividef(1.f, sum.w);

    int p0 = ii * 96 + jj0;
    float4 t4 = {acc.x * inv.x, acc.y * inv.y, acc.z * inv.z, acc.w * inv.w};
    __stcs((float4*)(out + T_OFF + (n * 64 + o) * 9216 + p0), t4);

    float4 pAdd;
    if (o < 32) {
        pAdd = *(const float4*)(px + o * 96 + jj0);
    } else {
        float v = py[(o - 32) * 96 + ii];
        pAdd = make_float4(v, v, v, v);
    }
    int wB = W_OFF + (n * 512 + o) * 9216 + p0;      // + h*589824
    int pB = P_OFF + (n * 512 + o) * 9216 + p0;
    int mB = n * 256 + (o & 31);                     // + h*32
    #pragma unroll
    for (int h = 0; h < 8; h++) {
        float4 w4 = {e[h].x * inv.x, e[h].y * inv.y, e[h].z * inv.z, e[h].w * inv.w};
        __stcs((float4*)(out + wB + h * 589824), w4);
        float m = g_M[mB + h * 32];
        float4 p4 = {m + pAdd.x, m + pAdd.y, m + pAdd.z, m + pAdd.w};
        __stcs((float4*)(out + pB + h * 589824), p4);
    }
}

// ---------------- launch ----------------------------------------------------
extern "C" void kernel_launch(void* const* d_in, const int* in_sizes, int n_in,
                              void* d_out, int out_size) {
    const float* X     = (const float*)d_in[0];
    const float* lin_w = (const float*)d_in[1];
    const float* lin_b = (const float*)d_in[2];
    const float* gam   = (const float*)d_in[3];
    const float* bet   = (const float*)d_in[4];
    const float* px    = (const float*)d_in[5];
    const float* py    = (const float*)d_in[6];
    const float* kw    = (const float*)d_in[7];
    const float* kb    = (const float*)d_in[8];
    const float* vw    = (const float*)d_in[9];
    const float* vb    = (const float*)d_in[10];
    const float* sw    = (const float*)d_in[11];
    const float* sb    = (const float*)d_in[12];
    float* out = (float*)d_out;

    k_embed<<<8, 256>>>(X, lin_w, lin_b, gam, bet, out + M_OFF);
    k_tab1<<<224, 256>>>(kw, kb, vw, vb, px, py, sw);
    k_tab2<<<576, 256>>>();
    k_tab3<<<5568, 256>>>(sb);
    k_main<<<dim3(6, 64, 8), dim3(24, 16)>>>(px, py, out);
}

// round 9
// speedup vs baseline: 1.2999x; 1.0636x over previous
#include <cuda_runtime.h>

// Shapes (fixed): h=8, n=8, d=512, c=64, c2=32, i=96, kk=3
// Output layout: [ T (8*64*96*96) | M (8*8*32) | P (8*8*64*96*96) | w (same as P) ]
#define T_OFF   0
#define M_OFF   4718592
#define P_OFF   4720640
#define W_OFF   42469376
#define INV24   (1.0f/24.0f)

// ---------------- scratch (device globals; no allocation) ----------------
__device__ __align__(16) float g_M[2048];                       // [n][h][32]
__device__ __align__(16) float g_Ak[4096],  g_Av[4096];         // [n][h][64]
__device__ __align__(16) float g_Bxk[49152], g_Byk[49152];      // [h][64][96]
__device__ __align__(16) float g_Bxv[49152], g_Byv[49152];      // [h][64][96]
__device__ __align__(16) float g_swX[36864], g_swY[36864];      // [cls][tap][o][cin]
__device__ __align__(16) float g_U[36864];                      // [n][h][o][xc][ky]
__device__ __align__(16) float g_Vx[442368], g_Vy[442368];      // [h][o][cls][tap][96]
__device__ __align__(16) float g_EX[147456];                    // [h][o][yc][96]
__device__ __align__(16) float g_EY[1179648];                   // [n][h][o][xc][96]
__device__ __align__(16) float g_VY[393216];                    // [n][h][o][96]

// ---- K1 (fused): per-head [embed -> axes -> btab] (b<8) | swtab (8..15) ----
__global__ void k_setup(const float* __restrict__ X, const float* __restrict__ lw,
                        const float* __restrict__ lb, const float* __restrict__ gam,
                        const float* __restrict__ bet,
                        const float* __restrict__ kw, const float* __restrict__ kb,
                        const float* __restrict__ vw, const float* __restrict__ vb,
                        const float* __restrict__ px, const float* __restrict__ py,
                        const float* __restrict__ sw, float* __restrict__ outM) {
    int b = blockIdx.x, t = threadIdx.x;
    if (b >= 8) {
        // ---- swtab: border-class conv weight tables (4096 items, 8 blocks) ----
        #pragma unroll
        for (int k = 0; k < 2; k++) {
            int tt = (b - 8) * 512 + k * 256 + t;   // (o,cin) pair
            float s[3][3];
            const float* p = sw + tt * 9;
            #pragma unroll
            for (int ky = 0; ky < 3; ky++)
                #pragma unroll
                for (int kx = 0; kx < 3; kx++) s[ky][kx] = p[ky * 3 + kx];
            #pragma unroll
            for (int xc = 0; xc < 3; xc++)
                #pragma unroll
                for (int ky = 0; ky < 3; ky++) {
                    float v = (xc == 0) ? (s[ky][1] + s[ky][2])
                            : (xc == 1) ? (s[ky][0] + s[ky][1] + s[ky][2])
                                        : (s[ky][0] + s[ky][1]);
                    g_swX[(xc * 3 + ky) * 4096 + tt] = v;
                }
            #pragma unroll
            for (int yc = 0; yc < 3; yc++)
                #pragma unroll
                for (int kx = 0; kx < 3; kx++) {
                    float v = (yc == 0) ? (s[1][kx] + s[2][kx])
                            : (yc == 1) ? (s[0][kx] + s[1][kx] + s[2][kx])
                                        : (s[0][kx] + s[1][kx]);
                    g_swY[(yc * 3 + kx) * 4096 + tt] = v;
                }
        }
        return;
    }
    int h = b;
    __shared__ float Xs[4096];
    __shared__ float ys[256];
    __shared__ float Ms[256];     // M[n][c] for this head
    __shared__ float mu_s[32], iv_s[32];
    const float* Xh = X + h * 4096;
    for (int k = t; k < 4096; k += 256) Xs[k] = Xh[k];
    __syncthreads();

    // ---- linear (float4 weight loads) ----
    int nn = t >> 5, cc = t & 31;
    const float4* wr = (const float4*)(lw + (h * 32 + cc) * 512);
    const float4* xr = (const float4*)(Xs + nn * 512);
    float acc = 0.f;
    #pragma unroll 8
    for (int d = 0; d < 128; d++) {
        float4 a = xr[d], w = wr[d];
        acc += a.x * w.x + a.y * w.y + a.z * w.z + a.w * w.w;
    }
    acc += lb[h * 32 + cc];
    ys[t] = acc;
    __syncthreads();
    if (t < 32) {
        float m = 0.f;
        for (int j = 0; j < 8; j++) m += ys[j * 32 + t];
        m *= 0.125f;
        float v = 0.f;
        for (int j = 0; j < 8; j++) { float d0 = ys[j * 32 + t] - m; v += d0 * d0; }
        v *= 0.125f;
        mu_s[t] = m;
        iv_s[t] = rsqrtf(v + 1e-5f);
    }
    __syncthreads();
    float val = (acc - mu_s[cc]) * iv_s[cc] * gam[h * 32 + cc] + bet[h * 32 + cc];
    val = fmaxf(val, 0.f);
    Ms[t] = val;
    int midx = (nn * 8 + h) * 32 + cc;
    g_M[midx]  = val;
    outM[midx] = val;
    __syncthreads();

    // ---- axes: A_k/A_v (512 items: n x d) ----
    for (int k = t; k < 512; k += 256) {
        int d = k & 63, n2 = k >> 6;
        const float* kwr = kw + (h * 64 + d) * 64;
        const float* vwr = vw + (h * 64 + d) * 64;
        const float* Mr  = Ms + n2 * 32;
        float ak = 0.f, av = 0.f;
        #pragma unroll 8
        for (int c = 0; c < 32; c++) {
            float m = Mr[c];
            ak += (kwr[c] + kwr[c + 32]) * m;
            av += (vwr[c] + vwr[c + 32]) * m;
        }
        g_Ak[(n2 * 8 + h) * 64 + d] = ak + kb[h * 64 + d];
        g_Av[(n2 * 8 + h) * 64 + d] = av + vb[h * 64 + d];
    }

    // ---- btab: Bx/By tables (6144 items: d x pos) ----
    for (int k = t; k < 6144; k += 256) {
        int pos = k % 96, d = k / 96;
        const float* kwr = kw + (h * 64 + d) * 64;
        const float* vwr = vw + (h * 64 + d) * 64;
        float bxk = 0.f, byk = 0.f, bxv = 0.f, byv = 0.f;
        #pragma unroll 8
        for (int c = 0; c < 32; c++) {
            float pxv = px[c * 96 + pos];
            float pyv = py[c * 96 + pos];
            bxk += kwr[c]      * pxv;
            byk += kwr[c + 32] * pyv;
            bxv += vwr[c]      * pxv;
            byv += vwr[c + 32] * pyv;
        }
        int idx = (h * 64 + d) * 96 + pos;
        g_Bxk[idx] = bxk; g_Byk[idx] = byk; g_Bxv[idx] = bxv; g_Byv[idx] = byv;
    }
}

// --------- K2 (fused): u (b<144) | vtab4 (144..575, float4) ---------------
__global__ void k_tab2() {
    int b = blockIdx.x, tid = threadIdx.x;
    if (b < 144) {
        int t = b * 256 + tid;
        int tap = t % 3; int r = t / 3;
        int cls = r % 3; r /= 3;
        int o = r % 64;  r /= 64;
        int h = r % 8;   int n = r / 8;
        const float* wv = g_swX + (cls * 3 + tap) * 4096 + o * 64;
        const float* ap = g_Ak + (n * 8 + h) * 64;
        float acc = 0.f;
        #pragma unroll 8
        for (int c = 0; c < 64; c++) acc += wv[c] * ap[c];
        g_U[t] = acc;
    } else {
        int t = (b - 144) * 256 + tid;
        int q = t % 24; int r = t / 24;
        int tap = r % 3;  r /= 3;
        int cls = r % 3;  r /= 3;
        int o = r % 64;   int h = r / 64;
        const float* wx = g_swX + (cls * 3 + tap) * 4096 + o * 64;  // -> Vy
        const float* wy = g_swY + (cls * 3 + tap) * 4096 + o * 64;  // -> Vx
        const float* byp = g_Byk + h * 6144 + q * 4;
        const float* bxp = g_Bxk + h * 6144 + q * 4;
        float4 vy = {0,0,0,0}, vx = {0,0,0,0};
        #pragma unroll 8
        for (int c = 0; c < 64; c++) {
            float wxc = wx[c], wyc = wy[c];
            float4 by = *(const float4*)(byp + c * 96);
            float4 bx = *(const float4*)(bxp + c * 96);
            vy.x += wxc * by.x; vy.y += wxc * by.y; vy.z += wxc * by.z; vy.w += wxc * by.w;
            vx.x += wyc * bx.x; vx.y += wyc * bx.y; vx.z += wyc * bx.z; vx.w += wyc * bx.w;
        }
        int base = ((((h * 64 + o) * 3 + cls) * 3 + tap) * 96) + q * 4;
        *(float4*)(g_Vy + base) = vy;
        *(float4*)(g_Vx + base) = vx;
    }
}

// --------- K3 (fused): ex (b<576) | ey (576..5183) | vy4 (5184..5567) ------
__global__ void k_tab3(const float* __restrict__ sb) {
    int b = blockIdx.x, tid = threadIdx.x;
    if (b < 576) {
        int t = b * 256 + tid;
        int jj = t % 96; int r = t / 96;
        int yc = r % 3;  r /= 3;
        int o = r % 64;  int h = r / 64;
        int base = ((h * 64 + o) * 3 + yc) * 3 * 96;
        float acc = 0.f;
        #pragma unroll
        for (int kx = 0; kx < 3; kx++) {
            int j2 = jj + kx - 1;
            if (j2 >= 0 && j2 < 96) acc += g_Vx[base + kx * 96 + j2];
        }
        g_EX[t] = expf(acc * INV24);
    } else if (b < 5184) {
        int t = (b - 576) * 256 + tid;
        int ii = t % 96; int r = t / 96;
        int xc = r % 3;  r /= 3;
        int o = r % 64;  r /= 64;
        int h = r % 8;   int n = r / 8;
        int ub = (((n * 8 + h) * 64 + o) * 3 + xc) * 3;
        int vb = ((h * 64 + o) * 3 + xc) * 3 * 96;
        float acc = sb[o];
        #pragma unroll
        for (int ky = 0; ky < 3; ky++) {
            int i2 = ii + ky - 1;
            if (i2 >= 0 && i2 < 96) acc += g_U[ub + ky] + g_Vy[vb + ky * 96 + i2];
        }
        g_EY[t] = expf(acc * INV24);
    } else {
        int t = (b - 5184) * 256 + tid;
        int q = t % 24; int r = t / 24;
        int o = r % 64;  r /= 64;
        int h = r % 8;   int n = r / 8;
        float av = g_Av[(n * 8 + h) * 64 + o];
        float4 by = *(const float4*)(g_Byv + (h * 64 + o) * 96 + q * 4);
        float4 vout = {av + by.x, av + by.y, av + by.z, av + by.w};
        *(float4*)(g_VY + ((n * 8 + h) * 64 + o) * 96 + q * 4) = vout;
    }
}

// -------- K4: main — two-pass, low-register, float4 stores (T, w, P) -------
__global__ void __launch_bounds__(384, 3) k_main(const float* __restrict__ px,
                                                 const float* __restrict__ py,
                                                 float* __restrict__ out) {
    int jq  = threadIdx.x;                           // 0..23 -> 4 jj each
    int jj0 = jq * 4;
    int ii  = blockIdx.x * 16 + threadIdx.y;         // 0..95
    int o   = blockIdx.y;                            // 0..63
    int n   = blockIdx.z;                            // 0..7
    int yc  = (ii == 0) ? 0 : ((ii == 95) ? 2 : 1);
    int off0 = (jq == 0)  ? 0   : 96;                // xc offset for lane-element 0
    int off3 = (jq == 23) ? 192 : 96;                // xc offset for lane-element 3

    int eyB = (n * 512 + o) * 288 + ii;              // + h*18432 (+off)
    int exB = (o * 3 + yc) * 96 + jj0;               // + h*18432
    int vyB = (n * 512 + o) * 96 + ii;               // + h*6144
    int bxB = o * 96 + jj0;                          // + h*6144

    // ---- pass 1: sums (no e[] kept live) ----
    float s0 = 0.f, s1 = 0.f, s2 = 0.f, s3 = 0.f;
    float a0 = 0.f, a1 = 0.f, a2 = 0.f, a3 = 0.f;
    #pragma unroll
    for (int h = 0; h < 8; h++) {
        const float* ey = g_EY + eyB + h * 18432;
        float eyM = ey[96], ey0 = ey[off0], ey3 = ey[off3];
        float4 ex = *(const float4*)(g_EX + exB + h * 18432);
        float  vy = g_VY[vyB + h * 6144];
        float4 bx = *(const float4*)(g_Bxv + bxB + h * 6144);
        float e0 = ey0 * ex.x, e1 = eyM * ex.y, e2 = eyM * ex.z, e3 = ey3 * ex.w;
        s0 += e0; s1 += e1; s2 += e2; s3 += e3;
        a0 += e0 * (vy + bx.x); a1 += e1 * (vy + bx.y);
        a2 += e2 * (vy + bx.z); a3 += e3 * (vy + bx.w);
    }
    float i0 = __fdividef(1.f, s0), i1 = __fdividef(1.f, s1);
    float i2 = __fdividef(1.f, s2), i3 = __fdividef(1.f, s3);

    int p0 = ii * 96 + jj0;
    float4 t4 = {a0 * i0, a1 * i1, a2 * i2, a3 * i3};
    __stcs((float4*)(out + T_OFF + (n * 64 + o) * 9216 + p0), t4);

    float4 pAdd;
    if (o < 32) {
        pAdd = *(const float4*)(px + o * 96 + jj0);
    } else {
        float v = py[(o - 32) * 96 + ii];
        pAdd = make_float4(v, v, v, v);
    }
    int wB = W_OFF + (n * 512 + o) * 9216 + p0;      // + h*589824
    int pB = P_OFF + (n * 512 + o) * 9216 + p0;
    int mB = n * 256 + (o & 31);                     // + h*32

    // ---- pass 2: recompute e (L1-hot reloads), write w and P ----
    #pragma unroll
    for (int h = 0; h < 8; h++) {
        const float* ey = g_EY + eyB + h * 18432;
        float eyM = ey[96], ey0 = ey[off0], ey3 = ey[off3];
        float4 ex = *(const float4*)(g_EX + exB + h * 18432);
        float4 w4 = {ey0 * ex.x * i0, eyM * ex.y * i1,
                     eyM * ex.z * i2, ey3 * ex.w * i3};
        __stcs((float4*)(out + wB + h * 589824), w4);
        float m = g_M[mB + h * 32];
        float4 p4 = {m + pAdd.x, m + pAdd.y, m + pAdd.z, m + pAdd.w};
        __stcs((float4*)(out + pB + h * 589824), p4);
    }
}

// ---------------- launch ----------------------------------------------------
extern "C" void kernel_launch(void* const* d_in, const int* in_sizes, int n_in,
                              void* d_out, int out_size) {
    const float* X     = (const float*)d_in[0];
    const float* lin_w = (const float*)d_in[1];
    const float* lin_b = (const float*)d_in[2];
    const float* gam   = (const float*)d_in[3];
    const float* bet   = (const float*)d_in[4];
    const float* px    = (const float*)d_in[5];
    const float* py    = (const float*)d_in[6];
    const float* kw    = (const float*)d_in[7];
    const float* kb    = (const float*)d_in[8];
    const float* vw    = (const float*)d_in[9];
    const float* vb    = (const float*)d_in[10];
    const float* sw    = (const float*)d_in[11];
    const float* sb    = (const float*)d_in[12];
    float* out = (float*)d_out;

    k_setup<<<16, 256>>>(X, lin_w, lin_b, gam, bet, kw, kb, vw, vb, px, py, sw,
                         out + M_OFF);
    k_tab2<<<576, 256>>>();
    k_tab3<<<5568, 256>>>(sb);
    k_main<<<dim3(6, 64, 8), dim3(24, 16)>>>(px, py, out);
}